// round 16
// baseline (speedup 1.0000x reference)
#include <cuda_runtime.h>
#include <cuda_fp16.h>
#include <cstdint>

#define NN   50000
#define EE   800000
#define DD   128
#define RR   8
#define NSEG (NN*RR)                     // 400000 segments
#define NB_SCAN ((NSEG + 1023) / 1024)   // 391
#define AW   1152                        // A row: 1024 mean ([B][R][64]) + 128 root
#define KW   640                         // GEMM K per output block: 512 mean + 128 root
#define WTOT (2 * 2 * KW * 64)
#define HIST_N (NN * 32)                 // 1.6M threads: covers EE, NN*32, WTOT

// ---------------- device scratch ----------------
// NOTE: g_cnt and g_desc must be ZERO at the start of every kernel_launch call.
// They are zero at module load, and k_gemm(layer=1) -- the last kernel of each
// call, which never reads them -- re-zeroes them for the next call.
__device__ int    g_cnt[NSEG];
__device__ int    g_ptr[NSEG];
__device__ int    g_pos[NSEG];
__device__ int    g_srcs[EE];
__device__ unsigned long long g_desc[NB_SCAN];
__device__ __half g_A[(size_t)NN * AW];
__device__ __half g_feat[2][(size_t)NN * DD];    // [0]=x fp16, [1]=h fp16
__device__ __half g_W[WTOT];                     // [layer][block][k][64]

// ---------------- cp.async helpers ----------------
__device__ __forceinline__ void cp_async16(uint32_t dst, const void* src, int src_bytes) {
    asm volatile("cp.async.cg.shared.global [%0], [%1], 16, %2;"
                 :: "r"(dst), "l"(src), "r"(src_bytes));
}
__device__ __forceinline__ void cp_commit() { asm volatile("cp.async.commit_group;"); }
template <int N>
__device__ __forceinline__ void cp_wait() { asm volatile("cp.async.wait_group %0;" :: "n"(N)); }

// ---------------- histogram + fp16 x-convert + weight prep (fused; all independent) ----------------
// Launched over HIST_N (=1.6M) threads: covers all three guarded ranges.
__global__ void k_hist(const int* __restrict__ dst, const int* __restrict__ et,
                       const float* __restrict__ x,
                       const float* __restrict__ W1, const float* __restrict__ root1,
                       const float* __restrict__ W2, const float* __restrict__ root2) {
    int i = blockIdx.x * blockDim.x + threadIdx.x;
    if (i < EE) atomicAdd(&g_cnt[dst[i] * RR + et[i]], 1);
    if (i < NN * 32) {
        int n = i >> 5, lane = i & 31;
        float4 v = ((const float4*)x)[i];
        __half2* f = reinterpret_cast<__half2*>(&g_feat[0][(size_t)n * DD + lane * 4]);
        f[0] = __floats2half2_rn(v.x, v.y);
        f[1] = __floats2half2_rn(v.z, v.w);
    }
    if (i < WTOT) {
        int j = i;
        int l = j / (2 * KW * 64); j -= l * (2 * KW * 64);
        int b = j / (KW * 64);     j -= b * (KW * 64);
        int k = j / 64;
        int d = j - k * 64;
        const float* W    = l ? W2    : W1;
        const float* root = l ? root2 : root1;
        float v;
        if (k < 512) {
            int r = k >> 6, c = k & 63;
            v = W[((r * 2 + b) * 64 + c) * 64 + d];
        } else {
            int din = k - 512;
            v = root[din * 128 + b * 64 + d];
        }
        g_W[i] = __float2half(v);
    }
}

// single-kernel exclusive scan, decoupled lookback (g_desc pre-zeroed)
__global__ void k_scan() {
    int b = blockIdx.x;
    int tid = threadIdx.x;
    int i = b * 1024 + tid;
    int v = (i < NSEG) ? g_cnt[i] : 0;
    int lane = tid & 31, warp = tid >> 5;
    int x = v;
    #pragma unroll
    for (int d = 1; d < 32; d <<= 1) {
        int y = __shfl_up_sync(0xffffffffu, x, d);
        if (lane >= d) x += y;
    }
    __shared__ int ws[32];
    if (lane == 31) ws[warp] = x;
    __syncthreads();
    if (warp == 0) {
        int s = ws[lane];
        #pragma unroll
        for (int d = 1; d < 32; d <<= 1) {
            int y = __shfl_up_sync(0xffffffffu, s, d);
            if (lane >= d) s += y;
        }
        ws[lane] = s;
    }
    __syncthreads();
    int off0 = warp ? ws[warp - 1] : 0;
    int inc = x + off0;

    __shared__ int s_tot, s_exc;
    if (tid == 1023) {
        s_tot = inc;
        unsigned long long d = ((b == 0) ? (2ull << 32) : (1ull << 32)) | (unsigned)inc;
        atomicExch(&g_desc[b], d);
    }
    if (b == 0 && tid == 0) s_exc = 0;
    __syncthreads();

    if (b > 0 && tid < 32) {
        int exc = 0;
        int p = b - 1;
        while (true) {
            int pp = p - lane;
            unsigned long long d = (2ull << 32);
            if (pp >= 0) {
                do { d = *(volatile unsigned long long*)&g_desc[pp]; }
                while ((d >> 32) == 0ull);
            }
            int flag = (int)(d >> 32);
            int val  = (int)(d & 0xffffffffu);
            unsigned m = __ballot_sync(0xffffffffu, flag == 2);
            int contrib;
            if (m) {
                int l2 = __ffs(m) - 1;
                contrib = (lane <= l2) ? val : 0;
            } else {
                contrib = val;
            }
            #pragma unroll
            for (int o = 16; o; o >>= 1) contrib += __shfl_xor_sync(0xffffffffu, contrib, o);
            exc += contrib;
            if (m) break;
            p -= 32;
        }
        if (lane == 0) {
            s_exc = exc;
            atomicExch(&g_desc[b], (2ull << 32) | (unsigned)(exc + s_tot));
        }
    }
    __syncthreads();
    if (i < NSEG) {
        int p = inc - v + s_exc;
        g_ptr[i] = p;
        g_pos[i] = p;
    }
}

// ---------------- CSR scatter ----------------
__global__ void k_scat(const int* __restrict__ src, const int* __restrict__ dst,
                       const int* __restrict__ et) {
    int i = blockIdx.x * blockDim.x + threadIdx.x;
    if (i < EE) {
        int seg = dst[i] * RR + et[i];
        int p = atomicAdd(&g_pos[seg], 1);
        g_srcs[p] = src[i];
    }
}

// ---------------- aggregation: 2 warps/node, 4 relations each, HALF-WARP EDGE PAIRING ----------------
// Lanes 0-15 process edge j (dims lane*8..+8, one uint4), lanes 16-31 process edge j+1.
// Per-relation serial chain halves; cross-half shfl_xor(16) reduce at the end.
__global__ void k_agg(int layer) {
    const __half* feat = g_feat[layer];
    int gw = (blockIdx.x * blockDim.x + threadIdx.x) >> 5;   // global warp id
    int n = gw >> 1;             // node
    int rg = gw & 1;             // relation group: relations [rg*4, rg*4+4)
    int lane = threadIdx.x & 31;
    if (n >= NN) return;
    int half = lane >> 4, l16 = lane & 15;
    int seg0 = n * RR + rg * 4;
    int c_l = (lane < 4) ? __ldg(&g_cnt[seg0 + lane]) : 0;
    int p_l = (lane < 4) ? __ldg(&g_ptr[seg0 + lane]) : 0;
    int base = __shfl_sync(0xffffffffu, p_l, 0);
    int deg  = __shfl_sync(0xffffffffu, p_l + c_l, 3) - base;
    const uint4* fl = reinterpret_cast<const uint4*>(feat) + l16;   // row = 16 uint4

    float acc[4][8];
    #pragma unroll
    for (int r = 0; r < 4; ++r)
        #pragma unroll
        for (int q = 0; q < 8; ++q) acc[r][q] = 0.f;

    for (int e0 = 0; e0 < deg; e0 += 32) {
        int idx = ((e0 + lane) < deg) ? __ldg(&g_srcs[base + e0 + lane]) : 0;
        #pragma unroll
        for (int r = 0; r < 4; ++r) {
            int st = __shfl_sync(0xffffffffu, p_l, r) - base;
            int ct = __shfl_sync(0xffffffffu, c_l, r);
            int lo = max(st, e0);
            int hi = min(st + ct, e0 + 32);
            for (int j = lo; j < hi; j += 2) {
                int jj = j + half;
                int sel = min(jj, hi - 1) - e0;
                int s = __shfl_sync(0xffffffffu, idx, sel);
                uint4 v = make_uint4(0u, 0u, 0u, 0u);
                if (jj < hi) v = __ldg(fl + (size_t)s * 16);
                float2 f;
                f = __half22float2(*(__half2*)&v.x); acc[r][0] += f.x; acc[r][1] += f.y;
                f = __half22float2(*(__half2*)&v.y); acc[r][2] += f.x; acc[r][3] += f.y;
                f = __half22float2(*(__half2*)&v.z); acc[r][4] += f.x; acc[r][5] += f.y;
                f = __half22float2(*(__half2*)&v.w); acc[r][6] += f.x; acc[r][7] += f.y;
            }
        }
    }

    // cross-half reduce: even-edge sums (lanes 0-15) + odd-edge sums (lanes 16-31)
    #pragma unroll
    for (int r = 0; r < 4; ++r)
        #pragma unroll
        for (int q = 0; q < 8; ++q)
            acc[r][q] += __shfl_xor_sync(0xffffffffu, acc[r][q], 16);

    // per-relation scales (need all-lane shfl before the lane<16 guard)
    float scs[4];
    #pragma unroll
    for (int r = 0; r < 4; ++r) {
        int ct = __shfl_sync(0xffffffffu, c_l, r);
        scs[r] = 1.0f / (float)max(ct, 1);
    }

    __half* Arow = &g_A[(size_t)n * AW];
    if (lane < 16) {
        int d0 = l16 * 8;
        #pragma unroll
        for (int r = 0; r < 4; ++r) {
            int rr = rg * 4 + r;
            float sc = scs[r];
            int col = (d0 < 64) ? (rr * 64 + d0) : (512 + rr * 64 + (d0 - 64));
            uint4 o;
            __half2 h;
            h = __floats2half2_rn(acc[r][0] * sc, acc[r][1] * sc); o.x = *(uint32_t*)&h;
            h = __floats2half2_rn(acc[r][2] * sc, acc[r][3] * sc); o.y = *(uint32_t*)&h;
            h = __floats2half2_rn(acc[r][4] * sc, acc[r][5] * sc); o.z = *(uint32_t*)&h;
            h = __floats2half2_rn(acc[r][6] * sc, acc[r][7] * sc); o.w = *(uint32_t*)&h;
            *(uint4*)(Arow + col) = o;
        }
        // root columns: warp rg copies feat dims [rg*64, rg*64+64) -> A cols 1024+rg*64+..
        int c4 = rg * 64 + l16 * 4;
        uint2 rv = *(const uint2*)(feat + (size_t)n * DD + c4);
        *(uint2*)(Arow + 1024 + c4) = rv;
    }
}

// ---------------- GEMM: Out[:, 64b:64b+64] = A_b (Nx640) @ Wcat_b (640x64) ----------------
__global__ void __launch_bounds__(256) k_gemm(int layer, const float* __restrict__ bias,
                                              float* __restrict__ dout) {
    // layer 1 also re-zeroes g_cnt/g_desc for the NEXT kernel_launch call.
    if (layer == 1) {
        int bid = blockIdx.y * gridDim.x + blockIdx.x;
        int t = bid * 256 + threadIdx.x;
        int z = t * 2;
        if (z + 1 < NSEG) { g_cnt[z] = 0; g_cnt[z + 1] = 0; }
        if (t < NB_SCAN) g_desc[t] = 0ull;
    }

    __shared__ __half As[2][128][72];
    __shared__ __half Bs[2][64][72];
    const __half* B = g_W + ((size_t)layer * 2 + blockIdx.y) * KW * 64;
    int b = blockIdx.y;
    int row0 = blockIdx.x * 128;
    int tid = threadIdx.x, warp = tid >> 5, lane = tid & 31;

    float acc[8][4];
    #pragma unroll
    for (int i = 0; i < 8; ++i)
        #pragma unroll
        for (int j = 0; j < 4; ++j) acc[i][j] = 0.f;

    auto load_stage = [&](int st, int kt) {
        int k0 = kt * 64;
        int cb = (k0 < 512) ? (b * 512 + k0) : (512 + k0);
        #pragma unroll
        for (int i = tid; i < 1024; i += 256) {
            int r = i >> 3, c8 = (i & 7) * 8;
            int grow = row0 + r;
            int ok = (grow < NN);
            const void* src = g_A + (size_t)(ok ? grow : 0) * AW + cb + c8;
            uint32_t dst = (uint32_t)__cvta_generic_to_shared(&As[st][r][c8]);
            cp_async16(dst, src, ok ? 16 : 0);
        }
        #pragma unroll
        for (int i = tid; i < 512; i += 256) {
            int r = i >> 3, c8 = (i & 7) * 8;
            uint32_t dst = (uint32_t)__cvta_generic_to_shared(&Bs[st][r][c8]);
            cp_async16(dst, B + (size_t)(k0 + r) * 64 + c8, 16);
        }
        cp_commit();
    };

    load_stage(0, 0);

    for (int kt = 0; kt < 10; ++kt) {
        int st = kt & 1;
        if (kt < 9) {
            load_stage(st ^ 1, kt + 1);
            cp_wait<1>();
        } else {
            cp_wait<0>();
        }
        __syncthreads();

        #pragma unroll
        for (int ks = 0; ks < 64; ks += 16) {
            uint32_t a0, a1, a2, a3;
            {
                uint32_t addr = (uint32_t)__cvta_generic_to_shared(
                    &As[st][warp * 16 + (lane & 15)][ks + (lane >> 4) * 8]);
                asm volatile("ldmatrix.sync.aligned.m8n8.x4.shared.b16 {%0,%1,%2,%3},[%4];"
                             : "=r"(a0), "=r"(a1), "=r"(a2), "=r"(a3) : "r"(addr));
            }
            #pragma unroll
            for (int np = 0; np < 4; ++np) {
                uint32_t b0, b1, b2, b3;
                uint32_t addr = (uint32_t)__cvta_generic_to_shared(
                    &Bs[st][ks + (lane & 15)][np * 16 + (lane >> 4) * 8]);
                asm volatile("ldmatrix.sync.aligned.m8n8.x4.trans.shared.b16 {%0,%1,%2,%3},[%4];"
                             : "=r"(b0), "=r"(b1), "=r"(b2), "=r"(b3) : "r"(addr));
                asm volatile("mma.sync.aligned.m16n8k16.row.col.f32.f16.f16.f32 "
                             "{%0,%1,%2,%3},{%4,%5,%6,%7},{%8,%9},{%0,%1,%2,%3};"
                             : "+f"(acc[np*2][0]), "+f"(acc[np*2][1]),
                               "+f"(acc[np*2][2]), "+f"(acc[np*2][3])
                             : "r"(a0), "r"(a1), "r"(a2), "r"(a3), "r"(b0), "r"(b1));
                asm volatile("mma.sync.aligned.m16n8k16.row.col.f32.f16.f16.f32 "
                             "{%0,%1,%2,%3},{%4,%5,%6,%7},{%8,%9},{%0,%1,%2,%3};"
                             : "+f"(acc[np*2+1][0]), "+f"(acc[np*2+1][1]),
                               "+f"(acc[np*2+1][2]), "+f"(acc[np*2+1][3])
                             : "r"(a0), "r"(a1), "r"(a2), "r"(a3), "r"(b2), "r"(b3));
            }
        }
        __syncthreads();
    }

    // epilogue: + bias; layer 0 -> ReLU + fp16 h (g_feat[1] only); layer 1 -> fp32 out
    int rbase = row0 + warp * 16 + (lane >> 2);
    #pragma unroll
    for (int nt = 0; nt < 8; ++nt) {
        int col = b * 64 + nt * 8 + (lane & 3) * 2;
        float bv0 = bias[col], bv1 = bias[col + 1];
        #pragma unroll
        for (int h = 0; h < 2; ++h) {
            int row = rbase + h * 8;
            if (row < NN) {
                float v0 = acc[nt][h * 2 + 0] + bv0;
                float v1 = acc[nt][h * 2 + 1] + bv1;
                if (layer == 0) {
                    v0 = fmaxf(v0, 0.f); v1 = fmaxf(v1, 0.f);
                    *reinterpret_cast<__half2*>(&g_feat[1][(size_t)row * DD + col]) =
                        __floats2half2_rn(v0, v1);
                } else {
                    dout[(size_t)row * DD + col]     = v0;
                    dout[(size_t)row * DD + col + 1] = v1;
                }
            }
        }
    }
}

// ---------------- launcher ----------------
extern "C" void kernel_launch(void* const* d_in, const int* in_sizes, int n_in,
                              void* d_out, int out_size) {
    const float* x    = (const float*)d_in[0];
    const int*   ei   = (const int*)  d_in[1];
    const int*   et   = (const int*)  d_in[2];
    const float* W1   = (const float*)d_in[3];
    const float* root1= (const float*)d_in[4];
    const float* b1   = (const float*)d_in[5];
    const float* W2   = (const float*)d_in[6];
    const float* root2= (const float*)d_in[7];
    const float* b2   = (const float*)d_in[8];
    float* out = (float*)d_out;
    const int* src = ei;
    const int* dst = ei + EE;

    k_hist<<<(HIST_N + 255) / 256, 256>>>(dst, et, x, W1, root1, W2, root2);   // 0
    k_scan<<<NB_SCAN, 1024>>>();                                               // 1
    k_scat<<<(EE + 255) / 256, 256>>>(src, dst, et);                           // 2
    k_agg <<<(NN * 64 + 255) / 256, 256>>>(0);                                 // 3  <- profiled slot
    k_gemm<<<dim3((NN + 127) / 128, 2), 256>>>(0, b1, out);                    // 4
    k_agg <<<(NN * 64 + 255) / 256, 256>>>(1);                                 // 5
    k_gemm<<<dim3((NN + 127) / 128, 2), 256>>>(1, b2, out);                    // 6 (+ zero cnt/desc)
}

// round 17
// speedup vs baseline: 1.2414x; 1.2414x over previous
#include <cuda_runtime.h>
#include <cuda_fp16.h>
#include <cstdint>

#define NN   50000
#define EE   800000
#define DD   128
#define RR   8
#define NSEG (NN*RR)                     // 400000 segments
#define NB_SCAN ((NSEG + 1023) / 1024)   // 391
#define AW   1024                        // A row: 1024 mean ([B][R][64]); root read from g_feat
#define KW   640                         // GEMM K per output block: 512 mean + 128 root
#define WTOT (2 * 2 * KW * 64)
#define HIST_N (NN * 32)                 // 1.6M threads: covers EE, NN*32, WTOT

// ---------------- device scratch ----------------
// NOTE: g_cnt and g_desc must be ZERO at the start of every kernel_launch call.
// They are zero at module load, and k_gemm(layer=1) -- the last kernel of each
// call, which never reads them -- re-zeroes them for the next call.
__device__ int    g_cnt[NSEG];
__device__ int    g_ptr[NSEG];
__device__ int    g_pos[NSEG];
__device__ int    g_srcs[EE];
__device__ unsigned long long g_desc[NB_SCAN];
__device__ __half g_A[(size_t)NN * AW];
__device__ __half g_feat[2][(size_t)NN * DD];    // [0]=x fp16, [1]=h fp16
__device__ __half g_W[WTOT];                     // [layer][block][k][64]

// ---------------- cp.async helpers ----------------
__device__ __forceinline__ void cp_async16(uint32_t dst, const void* src, int src_bytes) {
    asm volatile("cp.async.cg.shared.global [%0], [%1], 16, %2;"
                 :: "r"(dst), "l"(src), "r"(src_bytes));
}
__device__ __forceinline__ void cp_commit() { asm volatile("cp.async.commit_group;"); }
template <int N>
__device__ __forceinline__ void cp_wait() { asm volatile("cp.async.wait_group %0;" :: "n"(N)); }

// ---------------- histogram + fp16 x-convert + weight prep (fused; all independent) ----------------
__global__ void k_hist(const int* __restrict__ dst, const int* __restrict__ et,
                       const float* __restrict__ x,
                       const float* __restrict__ W1, const float* __restrict__ root1,
                       const float* __restrict__ W2, const float* __restrict__ root2) {
    int i = blockIdx.x * blockDim.x + threadIdx.x;
    if (i < EE) atomicAdd(&g_cnt[dst[i] * RR + et[i]], 1);
    if (i < NN * 32) {
        int n = i >> 5, lane = i & 31;
        float4 v = ((const float4*)x)[i];
        __half2* f = reinterpret_cast<__half2*>(&g_feat[0][(size_t)n * DD + lane * 4]);
        f[0] = __floats2half2_rn(v.x, v.y);
        f[1] = __floats2half2_rn(v.z, v.w);
    }
    if (i < WTOT) {
        int j = i;
        int l = j / (2 * KW * 64); j -= l * (2 * KW * 64);
        int b = j / (KW * 64);     j -= b * (KW * 64);
        int k = j / 64;
        int d = j - k * 64;
        const float* W    = l ? W2    : W1;
        const float* root = l ? root2 : root1;
        float v;
        if (k < 512) {
            int r = k >> 6, c = k & 63;
            v = W[((r * 2 + b) * 64 + c) * 64 + d];
        } else {
            int din = k - 512;
            v = root[din * 128 + b * 64 + d];
        }
        g_W[i] = __float2half(v);
    }
}

// single-kernel exclusive scan, decoupled lookback (g_desc pre-zeroed)
__global__ void k_scan() {
    int b = blockIdx.x;
    int tid = threadIdx.x;
    int i = b * 1024 + tid;
    int v = (i < NSEG) ? g_cnt[i] : 0;
    int lane = tid & 31, warp = tid >> 5;
    int x = v;
    #pragma unroll
    for (int d = 1; d < 32; d <<= 1) {
        int y = __shfl_up_sync(0xffffffffu, x, d);
        if (lane >= d) x += y;
    }
    __shared__ int ws[32];
    if (lane == 31) ws[warp] = x;
    __syncthreads();
    if (warp == 0) {
        int s = ws[lane];
        #pragma unroll
        for (int d = 1; d < 32; d <<= 1) {
            int y = __shfl_up_sync(0xffffffffu, s, d);
            if (lane >= d) s += y;
        }
        ws[lane] = s;
    }
    __syncthreads();
    int off0 = warp ? ws[warp - 1] : 0;
    int inc = x + off0;

    __shared__ int s_tot, s_exc;
    if (tid == 1023) {
        s_tot = inc;
        unsigned long long d = ((b == 0) ? (2ull << 32) : (1ull << 32)) | (unsigned)inc;
        atomicExch(&g_desc[b], d);
    }
    if (b == 0 && tid == 0) s_exc = 0;
    __syncthreads();

    if (b > 0 && tid < 32) {
        int exc = 0;
        int p = b - 1;
        while (true) {
            int pp = p - lane;
            unsigned long long d = (2ull << 32);
            if (pp >= 0) {
                do { d = *(volatile unsigned long long*)&g_desc[pp]; }
                while ((d >> 32) == 0ull);
            }
            int flag = (int)(d >> 32);
            int val  = (int)(d & 0xffffffffu);
            unsigned m = __ballot_sync(0xffffffffu, flag == 2);
            int contrib;
            if (m) {
                int l2 = __ffs(m) - 1;
                contrib = (lane <= l2) ? val : 0;
            } else {
                contrib = val;
            }
            #pragma unroll
            for (int o = 16; o; o >>= 1) contrib += __shfl_xor_sync(0xffffffffu, contrib, o);
            exc += contrib;
            if (m) break;
            p -= 32;
        }
        if (lane == 0) {
            s_exc = exc;
            atomicExch(&g_desc[b], (2ull << 32) | (unsigned)(exc + s_tot));
        }
    }
    __syncthreads();
    if (i < NSEG) {
        int p = inc - v + s_exc;
        g_ptr[i] = p;
        g_pos[i] = p;
    }
}

// ---------------- CSR scatter ----------------
__global__ void k_scat(const int* __restrict__ src, const int* __restrict__ dst,
                       const int* __restrict__ et) {
    int i = blockIdx.x * blockDim.x + threadIdx.x;
    if (i < EE) {
        int seg = dst[i] * RR + et[i];
        int p = atomicAdd(&g_pos[seg], 1);
        g_srcs[p] = src[i];
    }
}

// ---------------- aggregation: 2 warps/node, 4 relations each (frozen round-15 form, no root copy) ----------------
__global__ void k_agg(int layer) {
    const __half* feat = g_feat[layer];
    int gw = (blockIdx.x * blockDim.x + threadIdx.x) >> 5;   // global warp id
    int n = gw >> 1;             // node
    int rg = gw & 1;             // relation group: relations [rg*4, rg*4+4)
    int lane = threadIdx.x & 31;
    if (n >= NN) return;
    int seg0 = n * RR + rg * 4;
    int c_l = (lane < 4) ? __ldg(&g_cnt[seg0 + lane]) : 0;
    int p_l = (lane < 4) ? __ldg(&g_ptr[seg0 + lane]) : 0;
    int base = __shfl_sync(0xffffffffu, p_l, 0);
    int deg  = __shfl_sync(0xffffffffu, p_l + c_l, 3) - base;

    float acc[4][4];
    #pragma unroll
    for (int r = 0; r < 4; ++r) {
        acc[r][0] = acc[r][1] = acc[r][2] = acc[r][3] = 0.f;
    }

    for (int e0 = 0; e0 < deg; e0 += 32) {
        int idx = ((e0 + lane) < deg) ? __ldg(&g_srcs[base + e0 + lane]) : 0;
        #pragma unroll
        for (int r = 0; r < 4; ++r) {
            int st = __shfl_sync(0xffffffffu, p_l, r) - base;
            int ct = __shfl_sync(0xffffffffu, c_l, r);
            int lo = max(st, e0);
            int hi = min(st + ct, e0 + 32);
            for (int j = lo; j < hi; ++j) {
                int s = __shfl_sync(0xffffffffu, idx, j - e0);
                uint2 v = __ldg((const uint2*)(feat + (size_t)s * DD + lane * 4));
                float2 f0 = __half22float2(*(__half2*)&v.x);
                float2 f1 = __half22float2(*(__half2*)&v.y);
                acc[r][0] += f0.x; acc[r][1] += f0.y;
                acc[r][2] += f1.x; acc[r][3] += f1.y;
            }
        }
    }

    int d0 = lane * 4;
    __half* Arow = &g_A[(size_t)n * AW];
    #pragma unroll
    for (int r = 0; r < 4; ++r) {
        int rr = rg * 4 + r;
        int ct = __shfl_sync(0xffffffffu, c_l, r);
        float sc = 1.0f / (float)max(ct, 1);
        int col = (d0 < 64) ? (rr * 64 + d0) : (512 + rr * 64 + (d0 - 64));
        __half2* o = reinterpret_cast<__half2*>(Arow + col);
        o[0] = __floats2half2_rn(acc[r][0] * sc, acc[r][1] * sc);
        o[1] = __floats2half2_rn(acc[r][2] * sc, acc[r][3] * sc);
    }
}

// ---------------- GEMM: Out[:, 64b:64b+64] = [A_mean_b | feat] (Nx640) @ Wcat_b (640x64) ----------------
__global__ void __launch_bounds__(256) k_gemm(int layer, const float* __restrict__ bias,
                                              float* __restrict__ dout) {
    // layer 1 also re-zeroes g_cnt/g_desc for the NEXT kernel_launch call.
    if (layer == 1) {
        int bid = blockIdx.y * gridDim.x + blockIdx.x;
        int t = bid * 256 + threadIdx.x;
        int z = t * 2;
        if (z + 1 < NSEG) { g_cnt[z] = 0; g_cnt[z + 1] = 0; }
        if (t < NB_SCAN) g_desc[t] = 0ull;
    }

    __shared__ __half As[2][128][72];
    __shared__ __half Bs[2][64][72];
    const __half* B = g_W + ((size_t)layer * 2 + blockIdx.y) * KW * 64;
    const __half* feat = g_feat[layer];
    int b = blockIdx.y;
    int row0 = blockIdx.x * 128;
    int tid = threadIdx.x, warp = tid >> 5, lane = tid & 31;

    float acc[8][4];
    #pragma unroll
    for (int i = 0; i < 8; ++i)
        #pragma unroll
        for (int j = 0; j < 4; ++j) acc[i][j] = 0.f;

    auto load_stage = [&](int st, int kt) {
        int k0 = kt * 64;
        #pragma unroll
        for (int i = tid; i < 1024; i += 256) {
            int r = i >> 3, c8 = (i & 7) * 8;
            int grow = row0 + r;
            int ok = (grow < NN);
            const __half* src;
            if (k0 < 512) {
                src = g_A + (size_t)(ok ? grow : 0) * AW + b * 512 + k0 + c8;
            } else {
                // root K-tiles read the feature matrix directly (cols k0-512 .. +64)
                src = feat + (size_t)(ok ? grow : 0) * DD + (k0 - 512) + c8;
            }
            uint32_t dst = (uint32_t)__cvta_generic_to_shared(&As[st][r][c8]);
            cp_async16(dst, src, ok ? 16 : 0);
        }
        #pragma unroll
        for (int i = tid; i < 512; i += 256) {
            int r = i >> 3, c8 = (i & 7) * 8;
            uint32_t dst = (uint32_t)__cvta_generic_to_shared(&Bs[st][r][c8]);
            cp_async16(dst, B + (size_t)(k0 + r) * 64 + c8, 16);
        }
        cp_commit();
    };

    load_stage(0, 0);

    for (int kt = 0; kt < 10; ++kt) {
        int st = kt & 1;
        if (kt < 9) {
            load_stage(st ^ 1, kt + 1);
            cp_wait<1>();
        } else {
            cp_wait<0>();
        }
        __syncthreads();

        #pragma unroll
        for (int ks = 0; ks < 64; ks += 16) {
            uint32_t a0, a1, a2, a3;
            {
                uint32_t addr = (uint32_t)__cvta_generic_to_shared(
                    &As[st][warp * 16 + (lane & 15)][ks + (lane >> 4) * 8]);
                asm volatile("ldmatrix.sync.aligned.m8n8.x4.shared.b16 {%0,%1,%2,%3},[%4];"
                             : "=r"(a0), "=r"(a1), "=r"(a2), "=r"(a3) : "r"(addr));
            }
            #pragma unroll
            for (int np = 0; np < 4; ++np) {
                uint32_t b0, b1, b2, b3;
                uint32_t addr = (uint32_t)__cvta_generic_to_shared(
                    &Bs[st][ks + (lane & 15)][np * 16 + (lane >> 4) * 8]);
                asm volatile("ldmatrix.sync.aligned.m8n8.x4.trans.shared.b16 {%0,%1,%2,%3},[%4];"
                             : "=r"(b0), "=r"(b1), "=r"(b2), "=r"(b3) : "r"(addr));
                asm volatile("mma.sync.aligned.m16n8k16.row.col.f32.f16.f16.f32 "
                             "{%0,%1,%2,%3},{%4,%5,%6,%7},{%8,%9},{%0,%1,%2,%3};"
                             : "+f"(acc[np*2][0]), "+f"(acc[np*2][1]),
                               "+f"(acc[np*2][2]), "+f"(acc[np*2][3])
                             : "r"(a0), "r"(a1), "r"(a2), "r"(a3), "r"(b0), "r"(b1));
                asm volatile("mma.sync.aligned.m16n8k16.row.col.f32.f16.f16.f32 "
                             "{%0,%1,%2,%3},{%4,%5,%6,%7},{%8,%9},{%0,%1,%2,%3};"
                             : "+f"(acc[np*2+1][0]), "+f"(acc[np*2+1][1]),
                               "+f"(acc[np*2+1][2]), "+f"(acc[np*2+1][3])
                             : "r"(a0), "r"(a1), "r"(a2), "r"(a3), "r"(b2), "r"(b3));
            }
        }
        __syncthreads();
    }

    // epilogue: + bias; layer 0 -> ReLU + fp16 h (g_feat[1] only); layer 1 -> fp32 out
    int rbase = row0 + warp * 16 + (lane >> 2);
    #pragma unroll
    for (int nt = 0; nt < 8; ++nt) {
        int col = b * 64 + nt * 8 + (lane & 3) * 2;
        float bv0 = bias[col], bv1 = bias[col + 1];
        #pragma unroll
        for (int h = 0; h < 2; ++h) {
            int row = rbase + h * 8;
            if (row < NN) {
                float v0 = acc[nt][h * 2 + 0] + bv0;
                float v1 = acc[nt][h * 2 + 1] + bv1;
                if (layer == 0) {
                    v0 = fmaxf(v0, 0.f); v1 = fmaxf(v1, 0.f);
                    *reinterpret_cast<__half2*>(&g_feat[1][(size_t)row * DD + col]) =
                        __floats2half2_rn(v0, v1);
                } else {
                    dout[(size_t)row * DD + col]     = v0;
                    dout[(size_t)row * DD + col + 1] = v1;
                }
            }
        }
    }
}

// ---------------- launcher ----------------
extern "C" void kernel_launch(void* const* d_in, const int* in_sizes, int n_in,
                              void* d_out, int out_size) {
    const float* x    = (const float*)d_in[0];
    const int*   ei   = (const int*)  d_in[1];
    const int*   et   = (const int*)  d_in[2];
    const float* W1   = (const float*)d_in[3];
    const float* root1= (const float*)d_in[4];
    const float* b1   = (const float*)d_in[5];
    const float* W2   = (const float*)d_in[6];
    const float* root2= (const float*)d_in[7];
    const float* b2   = (const float*)d_in[8];
    float* out = (float*)d_out;
    const int* src = ei;
    const int* dst = ei + EE;

    k_hist<<<(HIST_N + 255) / 256, 256>>>(dst, et, x, W1, root1, W2, root2);   // 0
    k_scan<<<NB_SCAN, 1024>>>();                                               // 1
    k_scat<<<(EE + 255) / 256, 256>>>(src, dst, et);                           // 2
    k_agg <<<(NN * 64 + 255) / 256, 256>>>(0);                                 // 3  <- profiled slot
    k_gemm<<<dim3((NN + 127) / 128, 2), 256>>>(0, b1, out);                    // 4
    k_agg <<<(NN * 64 + 255) / 256, 256>>>(1);                                 // 5
    k_gemm<<<dim3((NN + 127) / 128, 2), 256>>>(1, b2, out);                    // 6 (+ zero cnt/desc)
}